// round 3
// baseline (speedup 1.0000x reference)
#include <cuda_runtime.h>
#include <cstdint>

#define BS 2
#define NF 16
#define C  32
#define H  128
#define W  128
#define HW (H*W)
#define NM 8
#define NK 3
#define MID (NF/2)
#define CHUNK 128
#define NCH (HW/CHUNK)     // 128
#define FG 4               // frames per block
#define FSPLIT (NF/FG)     // 4

typedef unsigned long long ull;

// partials: [b][c][m][fg][ch]  (1 MiB) — every element written exactly once
__device__ float g_part[BS*C*NM*FSPLIT*NCH];
// pooled: [b][m][c]
__device__ float g_pooled[BS*NM*C];

__device__ __forceinline__ ull pack2(float a, float b) {
    ull r; asm("mov.b64 %0,{%1,%2};" : "=l"(r) : "f"(a), "f"(b)); return r;
}

// ---------------------------------------------------------------------------
// Fused kernel: grid (NCH, FSPLIT, BS), 512 threads (16 warps).
//   P1: stage mid-frame chunk (32c x 128px = 16 KB) to smem  (L2-hot re-reads)
//   P2: mask tile (8 x 128) -> smem (+ gmem write by fgroup MID/FG only)
//   P3: pool FG frames, warp owns 2 channels, LDG.128 + f32x2 FMAs
//   P4: warp reduce, write partials
// ---------------------------------------------------------------------------
__global__ void __launch_bounds__(512, 1)
fused_kernel(const float* __restrict__ dec,
             const float* __restrict__ seg_w,
             const float* __restrict__ seg_b,
             float* __restrict__ masks_out)
{
    __shared__ float sdec[C*CHUNK];    // 16 KB
    __shared__ float smask[NM*CHUNK];  // 4 KB
    __shared__ float sw[NM*C];
    __shared__ float sb[NM];

    const int tid = threadIdx.x;
    const int ch  = blockIdx.x;
    const int fg  = blockIdx.y;
    const int b   = blockIdx.z;

    if (tid < NM*C) sw[tid] = seg_w[tid];
    if (tid < NM)   sb[tid] = seg_b[tid];

    // ---- P1: mid-frame chunk, float4 coalesced (1024 float4s / 512 thr) ----
    {
        const float* src = dec + ((size_t)(b*NF + MID))*C*HW + (size_t)ch*CHUNK;
#pragma unroll
        for (int r = 0; r < 2; r++) {
            int k  = tid + r*512;          // 0..1023
            int c  = k >> 5;               // 0..31
            int q4 = k & 31;               // 32 float4 per 128-px row
            reinterpret_cast<float4*>(sdec + c*CHUNK)[q4] =
                reinterpret_cast<const float4*>(src + (size_t)c*HW)[q4];
        }
    }
    __syncthreads();

    // ---- P2: mask tile (1024 items / 512 thr) ----
#pragma unroll
    for (int r = 0; r < 2; r++) {
        int k  = tid + r*512;
        int m  = k >> 7;                   // 0..7
        int px = k & 127;
        float a = sb[m];
#pragma unroll
        for (int c = 0; c < C; c++)
            a += sdec[c*CHUNK + px] * sw[m*C + c];
        smask[m*CHUNK + px] = a;
        if (fg == MID/FG)
            masks_out[((size_t)b*NM + m)*HW + (size_t)ch*CHUNK + px] = a;
    }
    __syncthreads();

    // ---- P3: pooling. warp w -> channels {2w, 2w+1}; lane -> 4 px ----
    const int wid  = tid >> 5;
    const int lane = tid & 31;
    const int c0   = wid * 2;

    ull mkA[NM], mkB[NM];
#pragma unroll
    for (int m = 0; m < NM; m++) {
        float4 mv = reinterpret_cast<const float4*>(smask + m*CHUNK)[lane];
        mkA[m] = pack2(mv.x, mv.y);
        mkB[m] = pack2(mv.z, mv.w);
    }

    ull acc[2][NM];
#pragma unroll
    for (int j = 0; j < 2; j++)
#pragma unroll
        for (int m = 0; m < NM; m++) acc[j][m] = 0ULL;

    const float* fbase = dec + (((size_t)(b*NF + fg*FG))*C + c0)*HW + (size_t)ch*CHUNK;

#pragma unroll
    for (int f = 0; f < FG; f++) {
#pragma unroll
        for (int j = 0; j < 2; j++) {
            float4 v = reinterpret_cast<const float4*>(
                           fbase + ((size_t)f*C + j)*HW)[lane];
            ull v01 = pack2(v.x, v.y);
            ull v23 = pack2(v.z, v.w);
#pragma unroll
            for (int m = 0; m < NM; m++) {
                asm("fma.rn.f32x2 %0, %1, %2, %0;" : "+l"(acc[j][m]) : "l"(v01), "l"(mkA[m]));
                asm("fma.rn.f32x2 %0, %1, %2, %0;" : "+l"(acc[j][m]) : "l"(v23), "l"(mkB[m]));
            }
        }
    }

    // ---- P4: warp butterfly reduce ----
#pragma unroll
    for (int j = 0; j < 2; j++) {
#pragma unroll
        for (int m = 0; m < NM; m++) {
            float2 a = *reinterpret_cast<float2*>(&acc[j][m]);
            float s = a.x + a.y;
#pragma unroll
            for (int off = 16; off; off >>= 1)
                s += __shfl_xor_sync(0xffffffffu, s, off);
            if (lane == 0) {
                int c = c0 + j;
                g_part[((((size_t)b*C + c)*NM + m)*FSPLIT + fg)*NCH + ch] = s;
            }
        }
    }
}

// ---------------------------------------------------------------------------
// Reduce: one block per (b,c,m) row of FSPLIT*NCH = 512 floats -> pooled/NF
// grid 512, 128 threads, fully coalesced.
// ---------------------------------------------------------------------------
__global__ void reduce_kernel()
{
    const int row = blockIdx.x;            // (b*C + c)*NM + m
    const int tid = threadIdx.x;
    const float* src = g_part + (size_t)row * (FSPLIT*NCH);

    float s = src[tid] + src[tid+128] + src[tid+256] + src[tid+384];
#pragma unroll
    for (int off = 16; off; off >>= 1)
        s += __shfl_xor_sync(0xffffffffu, s, off);

    __shared__ float ws[4];
    if ((tid & 31) == 0) ws[tid >> 5] = s;
    __syncthreads();
    if (tid == 0) {
        float t = (ws[0] + ws[1] + ws[2] + ws[3]) * (1.0f / NF);
        int m = row & (NM-1);
        int c = (row / NM) & (C-1);
        int b = row / (NM*C);
        g_pooled[((size_t)b*NM + m)*C + c] = t;
    }
}

// ---------------------------------------------------------------------------
// Logits: 48 outputs, one block.
// ---------------------------------------------------------------------------
__global__ void logits_kernel(const float* __restrict__ lw,
                              const float* __restrict__ lb,
                              float* __restrict__ out)
{
    int t = threadIdx.x;                   // 64 threads, 48 active
    if (t >= BS*NM*NK) return;
    int k  = t % NK;
    int bm = t / NK;                       // b*NM + m
    const float* p = g_pooled + (size_t)bm*C;
    float acc = lb[k];
#pragma unroll
    for (int c = 0; c < C; c++) acc += p[c] * lw[k*C + c];
    out[t] = acc;
}

// ---------------------------------------------------------------------------
extern "C" void kernel_launch(void* const* d_in, const int* in_sizes, int n_in,
                              void* d_out, int out_size)
{
    const float* dec   = (const float*)d_in[0];
    const float* seg_w = (const float*)d_in[1];
    const float* seg_b = (const float*)d_in[2];
    const float* lw    = (const float*)d_in[3];
    const float* lb    = (const float*)d_in[4];

    float* out    = (float*)d_out;
    float* logits = out;                 // 48 floats
    float* masks  = out + BS*NM*NK;      // 262144 floats

    fused_kernel <<<dim3(NCH, FSPLIT, BS), 512>>>(dec, seg_w, seg_b, masks);
    reduce_kernel<<<BS*C*NM, 128>>>();
    logits_kernel<<<1, 64>>>(lw, lb, logits);
}

// round 4
// speedup vs baseline: 1.3243x; 1.3243x over previous
#include <cuda_runtime.h>
#include <cstdint>

#define BS 2
#define NF 16
#define C  32
#define H  128
#define W  128
#define HW (H*W)
#define NM 8
#define NK 3
#define MID (NF/2)

#define PCHUNK 64            // pixels per pool block
#define PNCH (HW/PCHUNK)     // 256 chunks
#define PFG 8                // frames per pool block
#define PFS (NF/PFG)         // 2 frame-splits
#define CG 4                 // channel groups of 8

typedef unsigned long long ull;

// partials: [b][c][m][fs][ch]  (rows of PFS*PNCH = 512 floats)
__device__ float g_part[BS*C*NM*PFS*PNCH];
__device__ float g_pooled[BS*NM*C];

// ---------------------------------------------------------------------------
// Masks: masks[b,m,px] = sum_c dec[b,MID,c,px]*sw[m,c] + sb[m]
// grid (HW/128, BS), 128 threads, 1 px/thread, 32 independent loads.
// ---------------------------------------------------------------------------
__global__ void __launch_bounds__(128)
masks_kernel(const float* __restrict__ dec,
             const float* __restrict__ seg_w,
             const float* __restrict__ seg_b,
             float* __restrict__ masks_out)
{
    __shared__ float sw[NM*C];
    __shared__ float sb[NM];
    const int tid = threadIdx.x;
    sw[tid]       = seg_w[tid];
    sw[tid + 128] = seg_w[tid + 128];
    if (tid < NM) sb[tid] = seg_b[tid];
    __syncthreads();

    const int b  = blockIdx.y;
    const int px = blockIdx.x * 128 + tid;
    const float* src = dec + ((size_t)(b*NF + MID))*C*HW + px;

    // 32 fully independent loads
    float v[C];
#pragma unroll
    for (int c = 0; c < C; c++) v[c] = src[(size_t)c*HW];

    float acc[NM];
#pragma unroll
    for (int m = 0; m < NM; m++) acc[m] = sb[m];
#pragma unroll
    for (int c = 0; c < C; c++)
#pragma unroll
        for (int m = 0; m < NM; m++) acc[m] += v[c] * sw[m*C + c];

#pragma unroll
    for (int m = 0; m < NM; m++)
        masks_out[((size_t)b*NM + m)*HW + px] = acc[m];
}

// ---------------------------------------------------------------------------
// Pool: pure stream, no smem. 256 thr = 8 warps, warp owns 1 channel.
// grid (PNCH, CG*PFS, BS). Lane -> pixel pair (2*lane) of the 64-px chunk.
// ---------------------------------------------------------------------------
__global__ void __launch_bounds__(256)
pool_kernel(const float* __restrict__ dec, const float* __restrict__ masks)
{
    const int tid  = threadIdx.x;
    const int wid  = tid >> 5;
    const int lane = tid & 31;

    const int ch = blockIdx.x;
    const int cg = blockIdx.y & (CG-1);
    const int fs = blockIdx.y >> 2;
    const int b  = blockIdx.z;
    const int c  = cg*8 + wid;

    // mask pixel-pairs for this chunk (L1/L2-hot: shared by all 8 warps)
    ull mk[NM];
#pragma unroll
    for (int m = 0; m < NM; m++)
        mk[m] = *reinterpret_cast<const ull*>(
            masks + ((size_t)b*NM + m)*HW + (size_t)ch*PCHUNK + 2*lane);

    ull acc[NM];
#pragma unroll
    for (int m = 0; m < NM; m++) acc[m] = 0ULL;

    const float* base = dec + (((size_t)(b*NF + fs*PFG))*C + c)*HW
                            + (size_t)ch*PCHUNK;

#pragma unroll
    for (int f = 0; f < PFG; f++) {
        ull v = reinterpret_cast<const ull*>(base + (size_t)f*C*HW)[lane];
#pragma unroll
        for (int m = 0; m < NM; m++)
            asm("fma.rn.f32x2 %0, %1, %2, %0;" : "+l"(acc[m]) : "l"(v), "l"(mk[m]));
    }

#pragma unroll
    for (int m = 0; m < NM; m++) {
        float2 a = *reinterpret_cast<float2*>(&acc[m]);
        float s = a.x + a.y;
#pragma unroll
        for (int off = 16; off; off >>= 1)
            s += __shfl_xor_sync(0xffffffffu, s, off);
        if (lane == 0)
            g_part[((((size_t)b*C + c)*NM + m)*PFS + fs)*PNCH + ch] = s;
    }
}

// ---------------------------------------------------------------------------
// Reduce: one block per (b,c,m) row of PFS*PNCH = 512 floats -> pooled/NF
// ---------------------------------------------------------------------------
__global__ void reduce_kernel()
{
    const int row = blockIdx.x;            // (b*C + c)*NM + m
    const int tid = threadIdx.x;            // 128
    const float* src = g_part + (size_t)row * (PFS*PNCH);

    float s = src[tid] + src[tid+128] + src[tid+256] + src[tid+384];
#pragma unroll
    for (int off = 16; off; off >>= 1)
        s += __shfl_xor_sync(0xffffffffu, s, off);

    __shared__ float ws[4];
    if ((tid & 31) == 0) ws[tid >> 5] = s;
    __syncthreads();
    if (tid == 0) {
        float t = (ws[0] + ws[1] + ws[2] + ws[3]) * (1.0f / NF);
        int m = row & (NM-1);
        int c = (row / NM) & (C-1);
        int b = row / (NM*C);
        g_pooled[((size_t)b*NM + m)*C + c] = t;
    }
}

// ---------------------------------------------------------------------------
__global__ void logits_kernel(const float* __restrict__ lw,
                              const float* __restrict__ lb,
                              float* __restrict__ out)
{
    int t = threadIdx.x;                   // 64 threads, 48 active
    if (t >= BS*NM*NK) return;
    int k  = t % NK;
    int bm = t / NK;
    const float* p = g_pooled + (size_t)bm*C;
    float acc = lb[k];
#pragma unroll
    for (int c = 0; c < C; c++) acc += p[c] * lw[k*C + c];
    out[t] = acc;
}

// ---------------------------------------------------------------------------
extern "C" void kernel_launch(void* const* d_in, const int* in_sizes, int n_in,
                              void* d_out, int out_size)
{
    const float* dec   = (const float*)d_in[0];
    const float* seg_w = (const float*)d_in[1];
    const float* seg_b = (const float*)d_in[2];
    const float* lw    = (const float*)d_in[3];
    const float* lb    = (const float*)d_in[4];

    float* out    = (float*)d_out;
    float* logits = out;                 // 48 floats
    float* masks  = out + BS*NM*NK;      // 262144 floats

    masks_kernel <<<dim3(HW/128, BS), 128>>>(dec, seg_w, seg_b, masks);
    pool_kernel  <<<dim3(PNCH, CG*PFS, BS), 256>>>(dec, masks);
    reduce_kernel<<<BS*C*NM, 128>>>();
    logits_kernel<<<1, 64>>>(lw, lb, logits);
}

// round 5
// speedup vs baseline: 1.6459x; 1.2428x over previous
#include <cuda_runtime.h>
#include <cstdint>

#define BS 2
#define NF 16
#define C  32
#define H  128
#define W  128
#define HW (H*W)
#define NM 8
#define NK 3
#define MID (NF/2)

#define PCHUNK 128           // pixels per pool block
#define PNCH (HW/PCHUNK)     // 128 chunks
#define CG 4                 // channel groups of 8 (one warp per channel)

typedef unsigned long long ull;

// partials: [b][c][m][ch]  (rows of PNCH = 128 floats, 256 KB total)
__device__ float g_part[BS*C*NM*PNCH];
__device__ float g_pooled[BS*NM*C];
__device__ int   g_ctr;          // zero-initialized; self-resets each launch

__device__ __forceinline__ ull pack2(float a, float b) {
    ull r; asm("mov.b64 %0,{%1,%2};" : "=l"(r) : "f"(a), "f"(b)); return r;
}

// ---------------------------------------------------------------------------
// Masks: masks[b,m,px] = sum_c dec[b,MID,c,px]*sw[m,c] + sb[m]
// grid (HW/256, BS) = 128 blocks, 128 threads, one pixel-PAIR per thread.
// 32 independent float2 loads per thread.
// ---------------------------------------------------------------------------
__global__ void __launch_bounds__(128)
masks_kernel(const float* __restrict__ dec,
             const float* __restrict__ seg_w,
             const float* __restrict__ seg_b,
             float* __restrict__ masks_out)
{
    __shared__ float sw[NM*C];
    __shared__ float sb[NM];
    const int tid = threadIdx.x;
    sw[tid]       = seg_w[tid];
    sw[tid + 128] = seg_w[tid + 128];
    if (tid < NM) sb[tid] = seg_b[tid];
    __syncthreads();

    const int b  = blockIdx.y;
    const int p2 = blockIdx.x * 128 + tid;        // pair index
    const float* src = dec + ((size_t)(b*NF + MID))*C*HW + 2*(size_t)p2;

    float2 v[C];
#pragma unroll
    for (int c = 0; c < C; c++)
        v[c] = *reinterpret_cast<const float2*>(src + (size_t)c*HW);

    float2 acc[NM];
#pragma unroll
    for (int m = 0; m < NM; m++) acc[m] = make_float2(sb[m], sb[m]);
#pragma unroll
    for (int c = 0; c < C; c++)
#pragma unroll
        for (int m = 0; m < NM; m++) {
            float w = sw[m*C + c];
            acc[m].x += v[c].x * w;
            acc[m].y += v[c].y * w;
        }

#pragma unroll
    for (int m = 0; m < NM; m++)
        *reinterpret_cast<float2*>(
            masks_out + ((size_t)b*NM + m)*HW + 2*(size_t)p2) = acc[m];
}

// ---------------------------------------------------------------------------
// Pool: pure stream, all 16 frames per block. 256 thr = 8 warps, warp owns
// one channel; lane owns 4 px (float4). grid (PNCH, CG, BS) = 1024 blocks.
// ---------------------------------------------------------------------------
__global__ void __launch_bounds__(256)
pool_kernel(const float* __restrict__ dec, const float* __restrict__ masks)
{
    const int tid  = threadIdx.x;
    const int wid  = tid >> 5;
    const int lane = tid & 31;

    const int ch = blockIdx.x;
    const int cg = blockIdx.y;
    const int b  = blockIdx.z;
    const int c  = cg*8 + wid;

    // mask quads for this chunk (L1-hot: all 8 warps read the same 4 KB)
    ull mkA[NM], mkB[NM];
#pragma unroll
    for (int m = 0; m < NM; m++) {
        float4 mv = reinterpret_cast<const float4*>(
            masks + ((size_t)b*NM + m)*HW + (size_t)ch*PCHUNK)[lane];
        mkA[m] = pack2(mv.x, mv.y);
        mkB[m] = pack2(mv.z, mv.w);
    }

    ull acc[NM];
#pragma unroll
    for (int m = 0; m < NM; m++) acc[m] = 0ULL;

    const float* base = dec + ((size_t)b*NF*C + c)*HW + (size_t)ch*PCHUNK;

#pragma unroll 4
    for (int f = 0; f < NF; f++) {
        float4 v = reinterpret_cast<const float4*>(base + (size_t)f*C*HW)[lane];
        ull v01 = pack2(v.x, v.y);
        ull v23 = pack2(v.z, v.w);
#pragma unroll
        for (int m = 0; m < NM; m++) {
            asm("fma.rn.f32x2 %0, %1, %2, %0;" : "+l"(acc[m]) : "l"(v01), "l"(mkA[m]));
            asm("fma.rn.f32x2 %0, %1, %2, %0;" : "+l"(acc[m]) : "l"(v23), "l"(mkB[m]));
        }
    }

#pragma unroll
    for (int m = 0; m < NM; m++) {
        float2 a = *reinterpret_cast<float2*>(&acc[m]);
        float s = a.x + a.y;
#pragma unroll
        for (int off = 16; off; off >>= 1)
            s += __shfl_xor_sync(0xffffffffu, s, off);
        if (lane == 0)
            g_part[(((size_t)b*C + c)*NM + m)*PNCH + ch] = s;
    }
}

// ---------------------------------------------------------------------------
// Reduce + logits: 512 blocks × 128 thr; block reduces one (b,c,m) row of
// 128 floats into pooled; the LAST block to finish computes the 48 logits.
// ---------------------------------------------------------------------------
__global__ void __launch_bounds__(128)
reduce_logits_kernel(const float* __restrict__ lw,
                     const float* __restrict__ lb,
                     float* __restrict__ out)
{
    const int row = blockIdx.x;            // (b*C + c)*NM + m
    const int tid = threadIdx.x;

    float s = g_part[(size_t)row*PNCH + tid];
#pragma unroll
    for (int off = 16; off; off >>= 1)
        s += __shfl_xor_sync(0xffffffffu, s, off);

    __shared__ float ws[4];
    __shared__ bool  is_last;
    if ((tid & 31) == 0) ws[tid >> 5] = s;
    __syncthreads();

    if (tid == 0) {
        float t = (ws[0] + ws[1] + ws[2] + ws[3]) * (1.0f / NF);
        int m = row & (NM-1);
        int c = (row / NM) & (C-1);
        int b = row / (NM*C);
        g_pooled[((size_t)b*NM + m)*C + c] = t;
        __threadfence();
        is_last = (atomicAdd(&g_ctr, 1) == gridDim.x - 1);
    }
    __syncthreads();

    if (is_last) {
        __threadfence();                   // acquire pooled writes
        if (tid < BS*NM*NK) {
            int k  = tid % NK;
            int bm = tid / NK;
            const float* p = g_pooled + (size_t)bm*C;
            float acc = lb[k];
#pragma unroll
            for (int c = 0; c < C; c++) acc += p[c] * lw[k*C + c];
            out[tid] = acc;
        }
        if (tid == 0) g_ctr = 0;           // reset for next graph replay
    }
}

// ---------------------------------------------------------------------------
extern "C" void kernel_launch(void* const* d_in, const int* in_sizes, int n_in,
                              void* d_out, int out_size)
{
    const float* dec   = (const float*)d_in[0];
    const float* seg_w = (const float*)d_in[1];
    const float* seg_b = (const float*)d_in[2];
    const float* lw    = (const float*)d_in[3];
    const float* lb    = (const float*)d_in[4];

    float* out    = (float*)d_out;
    float* logits = out;                 // 48 floats
    float* masks  = out + BS*NM*NK;      // 262144 floats

    masks_kernel        <<<dim3(HW/256, BS), 128>>>(dec, seg_w, seg_b, masks);
    pool_kernel         <<<dim3(PNCH, CG, BS), 256>>>(dec, masks);
    reduce_logits_kernel<<<BS*C*NM, 128>>>(lw, lb, logits);
}

// round 6
// speedup vs baseline: 1.6486x; 1.0017x over previous
#include <cuda_runtime.h>
#include <cstdint>

#define BS 2
#define NF 16
#define C  32
#define H  128
#define W  128
#define HW (H*W)
#define NM 8
#define NK 3
#define MID (NF/2)

#define PCHUNK 128           // pixels per pool block
#define PNCH (HW/PCHUNK)     // 128 chunks
#define CG 4                 // channel groups of 8 (one warp per channel)

#define MB_PAIRS 128         // pixel pairs per masks block
#define MB_SPLIT 4           // channel splits (8 channels each)

typedef unsigned long long ull;

// partials: [b][c][m][ch]  (rows of PNCH = 128 floats, 256 KB total)
__device__ float g_part[BS*C*NM*PNCH];
__device__ float g_pooled[BS*NM*C];
__device__ int   g_ctr;          // zero-initialized; self-resets each launch

__device__ __forceinline__ ull pack2(float a, float b) {
    ull r; asm("mov.b64 %0,{%1,%2};" : "=l"(r) : "f"(a), "f"(b)); return r;
}

// ---------------------------------------------------------------------------
// Masks: masks[b,m,px] = sum_c dec[b,MID,c,px]*sw[m,c] + sb[m]
// grid (HW/2/MB_PAIRS, BS) = (64,2), 512 threads.
// 4-way channel split: thread (p,h) loads 8 float2 (channels h*8..h*8+7),
// partials combined through smem; coalesced epilogue adds bias and stores.
// ---------------------------------------------------------------------------
__global__ void __launch_bounds__(512)
masks_kernel(const float* __restrict__ dec,
             const float* __restrict__ seg_w,
             const float* __restrict__ seg_b,
             float* __restrict__ masks_out)
{
    __shared__ float2 part[MB_SPLIT][NM][MB_PAIRS];   // 32 KB
    __shared__ float  sw[NM*C];

    const int tid = threadIdx.x;
    if (tid < NM*C) sw[tid] = seg_w[tid];
    __syncthreads();

    const int b     = blockIdx.y;
    const int pair0 = blockIdx.x * MB_PAIRS;
    const int p     = tid & (MB_PAIRS-1);     // pair within block
    const int h     = tid >> 7;               // 0..3 channel split

    const float* src = dec + ((size_t)(b*NF + MID))*C*HW + 2*(size_t)(pair0 + p);

    float2 v[8];
#pragma unroll
    for (int i = 0; i < 8; i++)
        v[i] = *reinterpret_cast<const float2*>(src + (size_t)(h*8 + i)*HW);

#pragma unroll
    for (int m = 0; m < NM; m++) {
        float2 a = make_float2(0.f, 0.f);
#pragma unroll
        for (int i = 0; i < 8; i++) {
            float w = sw[m*C + h*8 + i];
            a.x += v[i].x * w;
            a.y += v[i].y * w;
        }
        part[h][m][p] = a;
    }
    __syncthreads();

    // 8 masks x 128 pairs = 1024 float2 outputs / 512 threads = 2 each
#pragma unroll
    for (int r = 0; r < 2; r++) {
        int k  = tid + r*512;
        int m  = k >> 7;
        int pp = k & (MB_PAIRS-1);
        float2 a0 = part[0][m][pp], a1 = part[1][m][pp];
        float2 a2 = part[2][m][pp], a3 = part[3][m][pp];
        float bsc = seg_b[m];
        float2 o  = make_float2(a0.x+a1.x+a2.x+a3.x + bsc,
                                a0.y+a1.y+a2.y+a3.y + bsc);
        *reinterpret_cast<float2*>(
            masks_out + ((size_t)b*NM + m)*HW + 2*(size_t)(pair0 + pp)) = o;
    }
}

// ---------------------------------------------------------------------------
// Pool: pure stream, all 16 frames per block. 256 thr = 8 warps, warp owns
// one channel; lane owns 4 px (float4). grid (PNCH, CG, BS) = 1024 blocks.
// ---------------------------------------------------------------------------
__global__ void __launch_bounds__(256)
pool_kernel(const float* __restrict__ dec, const float* __restrict__ masks)
{
    const int tid  = threadIdx.x;
    const int wid  = tid >> 5;
    const int lane = tid & 31;

    const int ch = blockIdx.x;
    const int cg = blockIdx.y;
    const int b  = blockIdx.z;
    const int c  = cg*8 + wid;

    ull mkA[NM], mkB[NM];
#pragma unroll
    for (int m = 0; m < NM; m++) {
        float4 mv = reinterpret_cast<const float4*>(
            masks + ((size_t)b*NM + m)*HW + (size_t)ch*PCHUNK)[lane];
        mkA[m] = pack2(mv.x, mv.y);
        mkB[m] = pack2(mv.z, mv.w);
    }

    ull acc[NM];
#pragma unroll
    for (int m = 0; m < NM; m++) acc[m] = 0ULL;

    const float* base = dec + ((size_t)b*NF*C + c)*HW + (size_t)ch*PCHUNK;

#pragma unroll 4
    for (int f = 0; f < NF; f++) {
        float4 v = reinterpret_cast<const float4*>(base + (size_t)f*C*HW)[lane];
        ull v01 = pack2(v.x, v.y);
        ull v23 = pack2(v.z, v.w);
#pragma unroll
        for (int m = 0; m < NM; m++) {
            asm("fma.rn.f32x2 %0, %1, %2, %0;" : "+l"(acc[m]) : "l"(v01), "l"(mkA[m]));
            asm("fma.rn.f32x2 %0, %1, %2, %0;" : "+l"(acc[m]) : "l"(v23), "l"(mkB[m]));
        }
    }

#pragma unroll
    for (int m = 0; m < NM; m++) {
        float2 a = *reinterpret_cast<float2*>(&acc[m]);
        float s = a.x + a.y;
#pragma unroll
        for (int off = 16; off; off >>= 1)
            s += __shfl_xor_sync(0xffffffffu, s, off);
        if (lane == 0)
            g_part[(((size_t)b*C + c)*NM + m)*PNCH + ch] = s;
    }
}

// ---------------------------------------------------------------------------
// Reduce + logits: 512 blocks × 128 thr; block reduces one (b,c,m) row of
// 128 floats into pooled; the LAST block to finish computes the 48 logits.
// ---------------------------------------------------------------------------
__global__ void __launch_bounds__(128)
reduce_logits_kernel(const float* __restrict__ lw,
                     const float* __restrict__ lb,
                     float* __restrict__ out)
{
    const int row = blockIdx.x;            // (b*C + c)*NM + m
    const int tid = threadIdx.x;

    float s = g_part[(size_t)row*PNCH + tid];
#pragma unroll
    for (int off = 16; off; off >>= 1)
        s += __shfl_xor_sync(0xffffffffu, s, off);

    __shared__ float ws[4];
    __shared__ bool  is_last;
    if ((tid & 31) == 0) ws[tid >> 5] = s;
    __syncthreads();

    if (tid == 0) {
        float t = (ws[0] + ws[1] + ws[2] + ws[3]) * (1.0f / NF);
        int m = row & (NM-1);
        int c = (row / NM) & (C-1);
        int b = row / (NM*C);
        g_pooled[((size_t)b*NM + m)*C + c] = t;
        __threadfence();
        is_last = (atomicAdd(&g_ctr, 1) == gridDim.x - 1);
    }
    __syncthreads();

    if (is_last) {
        __threadfence();                   // acquire pooled writes
        if (tid < BS*NM*NK) {
            int k  = tid % NK;
            int bm = tid / NK;
            const float* p = g_pooled + (size_t)bm*C;
            float acc = lb[k];
#pragma unroll
            for (int c = 0; c < C; c++) acc += p[c] * lw[k*C + c];
            out[tid] = acc;
        }
        if (tid == 0) g_ctr = 0;           // reset for next graph replay
    }
}

// ---------------------------------------------------------------------------
extern "C" void kernel_launch(void* const* d_in, const int* in_sizes, int n_in,
                              void* d_out, int out_size)
{
    const float* dec   = (const float*)d_in[0];
    const float* seg_w = (const float*)d_in[1];
    const float* seg_b = (const float*)d_in[2];
    const float* lw    = (const float*)d_in[3];
    const float* lb    = (const float*)d_in[4];

    float* out    = (float*)d_out;
    float* logits = out;                 // 48 floats
    float* masks  = out + BS*NM*NK;      // 262144 floats

    masks_kernel        <<<dim3(HW/2/MB_PAIRS, BS), 512>>>(dec, seg_w, seg_b, masks);
    pool_kernel         <<<dim3(PNCH, CG, BS), 256>>>(dec, masks);
    reduce_logits_kernel<<<BS*C*NM, 128>>>(lw, lb, logits);
}